// round 2
// baseline (speedup 1.0000x reference)
#include <cuda_runtime.h>
#include <math.h>
#include <stdint.h>

#define PL 512
#define EL 128
#define SS 640
#define TH 960
#define EH 720
#define TI 2560
#define EI 2048
#define NH 15
#define NKV 5
#define HD 64
#define LAYERS 16

// ---------------- scratch (device globals; no allocation allowed) ----------
__device__ float g_vlm[PL * TH];
__device__ float g_exp[EL * EH];
__device__ float g_hv [PL * TH];
__device__ float g_he [EL * EH];
__device__ float g_q  [SS * NH * HD];
__device__ float g_k  [SS * NKV * HD];
__device__ float g_v  [SS * NKV * HD];
__device__ float g_ke [PL * NKV * HD];
__device__ float g_ve [PL * NKV * HD];
__device__ float g_att[SS * NH * HD];
__device__ float g_g  [PL * TI];
__device__ float g_u  [PL * TI];

// ================= TF32 tensor-core GEMM =================
// C[M,N] = (ACCUM? C : 0) + A[M,K] @ B[K,N], fp32 in/out, tf32 mma.sync.
// Block tile 64x64, BK=32, 128 threads = 4 warps, each warp 32x32.
// Smem layouts: As[m][k] stride 36, Bs[n][k] stride 36.
// Fragment-load bank = (4*idx + k) % 32 == lane -> conflict-free.
// Requires M % 64 == 0 (true here: 512/128), K % 16 == 0, N % 16 == 0.

#define GBM 64
#define GBN 64
#define GBK 32
#define LSTRIDE 36

__device__ __forceinline__ uint32_t f2tf32(float x) {
    uint32_t r;
    asm("cvt.rna.tf32.f32 %0, %1;" : "=r"(r) : "f"(x));
    return r;
}

template <int ACCUM>
__global__ __launch_bounds__(128)
void tf32_gemm(const float* __restrict__ A, const float* __restrict__ B,
               float* __restrict__ C, int M, int N, int K) {
    __shared__ uint32_t As[GBM * LSTRIDE];   // [m][k]
    __shared__ uint32_t Bs[GBN * LSTRIDE];   // [n][k]  (transposed)

    const int tid  = threadIdx.x;
    const int lane = tid & 31;
    const int warp = tid >> 5;         // 0..3
    const int wm   = warp & 1;         // m half (0/1)
    const int wn   = warp >> 1;        // n half (0/1)
    const int m0   = blockIdx.y * GBM;
    const int n0   = blockIdx.x * GBN;
    const int gid  = lane >> 2;        // 0..7
    const int tig  = lane & 3;         // 0..3

    float c[2][4][4] = {};             // [mtile16][ntile8][4]

    // global->smem loader mapping
    const int ar = tid >> 1;           // A row 0..63
    const int ac = (tid & 1) * 16;     // A col base (16 floats per thread)
    const int br = tid >> 2;           // B k-row 0..31
    const int bc = (tid & 3) * 16;     // B n base (16 floats per thread)

    for (int k0 = 0; k0 < K; k0 += GBK) {
        // ---- A tile 64x32 ----
#pragma unroll
        for (int i = 0; i < 16; i += 4) {
            int gk = k0 + ac + i;
            float4 val = make_float4(0.f, 0.f, 0.f, 0.f);
            if (gk < K) val = *(const float4*)&A[(size_t)(m0 + ar) * K + gk];
            uint32_t* dst = &As[ar * LSTRIDE + ac + i];
            dst[0] = f2tf32(val.x); dst[1] = f2tf32(val.y);
            dst[2] = f2tf32(val.z); dst[3] = f2tf32(val.w);
        }
        // ---- B tile 32x64 -> Bs[n][k] ----
        {
            int gk = k0 + br;
            bool kok = (gk < K);
#pragma unroll
            for (int i = 0; i < 16; i += 4) {
                int gn = n0 + bc + i;
                float4 val = make_float4(0.f, 0.f, 0.f, 0.f);
                if (kok && gn < N) val = *(const float4*)&B[(size_t)gk * N + gn];
                Bs[(bc + i + 0) * LSTRIDE + br] = f2tf32(val.x);
                Bs[(bc + i + 1) * LSTRIDE + br] = f2tf32(val.y);
                Bs[(bc + i + 2) * LSTRIDE + br] = f2tf32(val.z);
                Bs[(bc + i + 3) * LSTRIDE + br] = f2tf32(val.w);
            }
        }
        __syncthreads();

#pragma unroll
        for (int kk = 0; kk < GBK; kk += 8) {
            uint32_t a[2][4], b[4][2];
#pragma unroll
            for (int mt = 0; mt < 2; mt++) {
                int mb = wm * 32 + mt * 16;
                a[mt][0] = As[(mb + gid    ) * LSTRIDE + kk + tig];
                a[mt][1] = As[(mb + gid + 8) * LSTRIDE + kk + tig];
                a[mt][2] = As[(mb + gid    ) * LSTRIDE + kk + tig + 4];
                a[mt][3] = As[(mb + gid + 8) * LSTRIDE + kk + tig + 4];
            }
#pragma unroll
            for (int nt = 0; nt < 4; nt++) {
                int nb = wn * 32 + nt * 8;
                b[nt][0] = Bs[(nb + gid) * LSTRIDE + kk + tig];
                b[nt][1] = Bs[(nb + gid) * LSTRIDE + kk + tig + 4];
            }
#pragma unroll
            for (int mt = 0; mt < 2; mt++)
#pragma unroll
                for (int nt = 0; nt < 4; nt++) {
                    asm volatile(
                        "mma.sync.aligned.m16n8k8.row.col.f32.tf32.tf32.f32 "
                        "{%0,%1,%2,%3}, {%4,%5,%6,%7}, {%8,%9}, {%0,%1,%2,%3};"
                        : "+f"(c[mt][nt][0]), "+f"(c[mt][nt][1]),
                          "+f"(c[mt][nt][2]), "+f"(c[mt][nt][3])
                        : "r"(a[mt][0]), "r"(a[mt][1]),
                          "r"(a[mt][2]), "r"(a[mt][3]),
                          "r"(b[nt][0]), "r"(b[nt][1]));
                }
        }
        __syncthreads();
    }

    // ---- epilogue ----
#pragma unroll
    for (int mt = 0; mt < 2; mt++) {
#pragma unroll
        for (int nt = 0; nt < 4; nt++) {
            int gm = m0 + wm * 32 + mt * 16 + gid;
            int gn = n0 + wn * 32 + nt * 8 + tig * 2;
            if (gn < N) {
                size_t o0 = (size_t)gm * N + gn;
                size_t o1 = (size_t)(gm + 8) * N + gn;
                if (ACCUM) {
                    C[o0]     += c[mt][nt][0];
                    C[o0 + 1] += c[mt][nt][1];
                    C[o1]     += c[mt][nt][2];
                    C[o1 + 1] += c[mt][nt][3];
                } else {
                    C[o0]     = c[mt][nt][0];
                    C[o0 + 1] = c[mt][nt][1];
                    C[o1]     = c[mt][nt][2];
                    C[o1 + 1] = c[mt][nt][3];
                }
            }
        }
    }
}

static inline void gemm(const float* A, const float* B, float* C,
                        int M, int N, int K, bool accum) {
    dim3 grid((N + GBN - 1) / GBN, (M + GBM - 1) / GBM);
    if (accum) tf32_gemm<1><<<grid, 128>>>(A, B, C, M, N, K);
    else       tf32_gemm<0><<<grid, 128>>>(A, B, C, M, N, K);
}

// ---------------- RMSNorm ----------------
__global__ void rmsnorm_kernel(const float* __restrict__ x,
                               const float* __restrict__ w,
                               float* __restrict__ y, int D) {
    const int row = blockIdx.x;
    const float* xr = x + (size_t)row * D;
    float ss = 0.f;
    for (int i = threadIdx.x; i < D; i += 256) { float v = xr[i]; ss += v * v; }
    __shared__ float red[256];
    red[threadIdx.x] = ss;
    __syncthreads();
    for (int s = 128; s > 0; s >>= 1) {
        if (threadIdx.x < s) red[threadIdx.x] += red[threadIdx.x + s];
        __syncthreads();
    }
    float r = rsqrtf(red[0] / (float)D + 1e-5f);
    float* yr = y + (size_t)row * D;
    for (int i = threadIdx.x; i < D; i += 256) yr[i] = w[i] * xr[i] * r;
}

// ---------------- RoPE (in place) ----------------
__global__ void rope_kernel(float* __restrict__ x, int nrows, int nheads,
                            int pos_base) {
    int idx = blockIdx.x * blockDim.x + threadIdx.x;
    int total = nrows * nheads * 32;
    if (idx >= total) return;
    int d = idx & 31;
    int h = (idx >> 5) % nheads;
    int r = idx / (32 * nheads);
    float pos = (float)(pos_base + r);
    float ts = powf(10000.f, (float)d * (1.f / 32.f));
    float rad = pos / ts;
    float s, c;
    sincosf(rad, &s, &c);
    float* p = x + ((size_t)r * nheads + h) * HD;
    float x1 = p[d], x2 = p[d + 32];
    p[d]      = x1 * c - x2 * s;
    p[d + 32] = x2 * c + x1 * s;
}

// ---------------- Attention (SIMT fp32, unchanged) ----------------
__global__ __launch_bounds__(128)
void attn_kernel(const float* __restrict__ q, const float* __restrict__ k,
                 const float* __restrict__ v, float* __restrict__ out,
                 int nk, int prefix) {
    const int qi  = blockIdx.x;
    const int h   = blockIdx.y;
    const int kvh = h / 3;
    const int tid = threadIdx.x;

    __shared__ float qs[HD];
    __shared__ float sc[SS];
    __shared__ float red[128];

    const float* qr = q + ((size_t)qi * NH + h) * HD;
    if (tid < HD) qs[tid] = qr[tid];
    __syncthreads();

    int kmax = nk;
    if (prefix) kmax = (qi + 1 > prefix) ? (qi + 1) : prefix;

    float mx = -1e30f;
    for (int j = tid; j < kmax; j += 128) {
        const float* kr = k + ((size_t)j * NKV + kvh) * HD;
        float dot = 0.f;
#pragma unroll
        for (int d = 0; d < HD; d++) dot += qs[d] * kr[d];
        dot *= 0.125f;
        sc[j] = dot;
        mx = fmaxf(mx, dot);
    }
    red[tid] = mx;
    __syncthreads();
    for (int s = 64; s > 0; s >>= 1) {
        if (tid < s) red[tid] = fmaxf(red[tid], red[tid + s]);
        __syncthreads();
    }
    mx = red[0];
    __syncthreads();

    float sum = 0.f;
    for (int j = tid; j < kmax; j += 128) {
        float e = expf(sc[j] - mx);
        sc[j] = e;
        sum += e;
    }
    red[tid] = sum;
    __syncthreads();
    for (int s = 64; s > 0; s >>= 1) {
        if (tid < s) red[tid] += red[tid + s];
        __syncthreads();
    }
    float inv = 1.f / red[0];
    __syncthreads();

    const int d = tid & 63;
    const int half = tid >> 6;
    float acc = 0.f;
    for (int j = half; j < kmax; j += 2)
        acc += sc[j] * v[((size_t)j * NKV + kvh) * HD + d];
    red[tid] = acc;
    __syncthreads();
    if (tid < HD)
        out[((size_t)qi * NH + h) * HD + d] = (red[tid] + red[tid + 64]) * inv;
}

// ---------------- silu(g) * u ----------------
__global__ void silu_mul_kernel(const float* __restrict__ g,
                                const float* __restrict__ u,
                                float* __restrict__ m, int n) {
    int i = blockIdx.x * blockDim.x + threadIdx.x;
    if (i < n) {
        float x = g[i];
        float s = x / (1.f + expf(-x));
        m[i] = s * u[i];
    }
}

// ---------------- launch ----------------
static float* sym(const void* s) {
    void* p = nullptr;
    cudaGetSymbolAddress(&p, s);
    return (float*)p;
}

extern "C" void kernel_launch(void* const* d_in, const int* in_sizes, int n_in,
                              void* d_out, int out_size) {
    const float* vlm_embeds    = (const float*)d_in[0];
    const float* expert_embeds = (const float*)d_in[1];
    const float* w_vlm_q       = (const float*)d_in[2];
    const float* w_vlm_k       = (const float*)d_in[3];
    const float* w_vlm_v       = (const float*)d_in[4];
    const float* w_vlm_o       = (const float*)d_in[5];
    const float* w_vlm_ln1     = (const float*)d_in[6];
    const float* w_vlm_ln2     = (const float*)d_in[7];
    const float* w_vlm_gate    = (const float*)d_in[8];
    const float* w_vlm_up      = (const float*)d_in[9];
    const float* w_vlm_down    = (const float*)d_in[10];
    const float* w_vlm_fnorm   = (const float*)d_in[11];
    const float* w_exp_q       = (const float*)d_in[12];
    const float* w_exp_k_self  = (const float*)d_in[13];
    const float* w_exp_v_self  = (const float*)d_in[14];
    const float* w_exp_k_cross = (const float*)d_in[15];
    const float* w_exp_v_cross = (const float*)d_in[16];
    const float* w_exp_o       = (const float*)d_in[17];
    const float* w_exp_ln1     = (const float*)d_in[18];
    const float* w_exp_ln2     = (const float*)d_in[19];
    const float* w_exp_gate    = (const float*)d_in[20];
    const float* w_exp_up      = (const float*)d_in[21];
    const float* w_exp_down    = (const float*)d_in[22];
    const float* w_exp_fnorm   = (const float*)d_in[23];

    float* vlm = sym(g_vlm);
    float* exq = sym(g_exp);
    float* hv  = sym(g_hv);
    float* he  = sym(g_he);
    float* q   = sym(g_q);
    float* k   = sym(g_k);
    float* v   = sym(g_v);
    float* ke  = sym(g_ke);
    float* ve  = sym(g_ve);
    float* att = sym(g_att);
    float* gg  = sym(g_g);
    float* gu  = sym(g_u);

    cudaMemcpyAsync(vlm, vlm_embeds,    (size_t)PL * TH * sizeof(float),
                    cudaMemcpyDeviceToDevice, 0);
    cudaMemcpyAsync(exq, expert_embeds, (size_t)EL * EH * sizeof(float),
                    cudaMemcpyDeviceToDevice, 0);

    for (int li = 0; li < LAYERS; li++) {
        rmsnorm_kernel<<<PL, 256>>>(vlm, w_vlm_ln1 + (size_t)li * TH, hv, TH);
        rmsnorm_kernel<<<EL, 256>>>(exq, w_exp_ln1 + (size_t)li * EH, he, EH);

        gemm(hv, w_vlm_q + (size_t)li * TH * (NH * HD),  q,                PL, NH * HD,  TH, false);
        gemm(hv, w_vlm_k + (size_t)li * TH * (NKV * HD), k,                PL, NKV * HD, TH, false);
        gemm(hv, w_vlm_v + (size_t)li * TH * (NKV * HD), v,                PL, NKV * HD, TH, false);
        gemm(he, w_exp_q + (size_t)li * EH * (NH * HD),  q + PL * NH * HD, EL, NH * HD,  EH, false);

        if ((li & 1) == 0) {
            gemm(he, w_exp_k_self + (size_t)(li / 2) * EH * (NKV * HD),
                 k + PL * NKV * HD, EL, NKV * HD, EH, false);
            gemm(he, w_exp_v_self + (size_t)(li / 2) * EH * (NKV * HD),
                 v + PL * NKV * HD, EL, NKV * HD, EH, false);
            {
                int t = SS * NH * 32;
                rope_kernel<<<(t + 255) / 256, 256>>>(q, SS, NH, 0);
            }
            {
                int t = SS * NKV * 32;
                rope_kernel<<<(t + 255) / 256, 256>>>(k, SS, NKV, 0);
            }
            attn_kernel<<<dim3(SS, NH), 128>>>(q, k, v, att, SS, PL);
        } else {
            {
                int t = SS * NH * 32;
                rope_kernel<<<(t + 255) / 256, 256>>>(q, SS, NH, 0);
            }
            {
                int t = PL * NKV * 32;
                rope_kernel<<<(t + 255) / 256, 256>>>(k, PL, NKV, 0);
            }
            gemm(k, w_exp_k_cross + (size_t)(li / 2) * (NKV * HD) * (NKV * HD),
                 ke, PL, NKV * HD, NKV * HD, false);
            gemm(v, w_exp_v_cross + (size_t)(li / 2) * (NKV * HD) * (NKV * HD),
                 ve, PL, NKV * HD, NKV * HD, false);
            attn_kernel<<<dim3(PL, NH), 128>>>(q, k, v, att, PL, 0);
            attn_kernel<<<dim3(EL, NH), 128>>>(q + PL * NH * HD, ke, ve,
                                               att + PL * NH * HD, PL, 0);
        }

        gemm(att, w_vlm_o + (size_t)li * (NH * HD) * TH, vlm, PL, TH, NH * HD, true);
        rmsnorm_kernel<<<PL, 256>>>(vlm, w_vlm_ln2 + (size_t)li * TH, hv, TH);
        gemm(hv, w_vlm_gate + (size_t)li * TH * TI, gg, PL, TI, TH, false);
        gemm(hv, w_vlm_up   + (size_t)li * TH * TI, gu, PL, TI, TH, false);
        silu_mul_kernel<<<(PL * TI + 255) / 256, 256>>>(gg, gu, gg, PL * TI);
        gemm(gg, w_vlm_down + (size_t)li * TI * TH, vlm, PL, TH, TI, true);

        gemm(att + PL * NH * HD, w_exp_o + (size_t)li * (NH * HD) * EH,
             exq, EL, EH, NH * HD, true);
        rmsnorm_kernel<<<EL, 256>>>(exq, w_exp_ln2 + (size_t)li * EH, he, EH);
        gemm(he, w_exp_gate + (size_t)li * EH * EI, gg, EL, EI, EH, false);
        gemm(he, w_exp_up   + (size_t)li * EH * EI, gu, EL, EI, EH, false);
        silu_mul_kernel<<<(EL * EI + 255) / 256, 256>>>(gg, gu, gg, EL * EI);
        gemm(gg, w_exp_down + (size_t)li * EI * EH, exq, EL, EH, EI, true);
    }

    float* out = (float*)d_out;
    rmsnorm_kernel<<<PL, 256>>>(vlm, w_vlm_fnorm, out, TH);
    rmsnorm_kernel<<<EL, 256>>>(exq, w_exp_fnorm, out + (size_t)PL * TH, EH);
}

// round 3
// speedup vs baseline: 2.0497x; 2.0497x over previous
#include <cuda_runtime.h>
#include <math.h>
#include <stdint.h>

#define PL 512
#define EL 128
#define SS 640
#define TH 960
#define EH 720
#define TI 2560
#define EI 2048
#define NH 15
#define NKV 5
#define HD 64
#define LAYERS 16

// ---------------- scratch (device globals) ----------------
__device__ float g_vlm[PL * TH];
__device__ float g_exp[EL * EH];
__device__ float g_hv [PL * TH];
__device__ float g_he [EL * EH];
__device__ float g_q  [SS * NH * HD];
__device__ float g_k  [SS * NKV * HD];
__device__ float g_v  [SS * NKV * HD];
__device__ float g_ke [PL * NKV * HD];
__device__ float g_ve [PL * NKV * HD];
__device__ float g_att[SS * NH * HD];
__device__ float g_g  [PL * TI];       // vlm MLP (stream 0)
__device__ float g_u  [PL * TI];
__device__ float g_ge [EL * EI];       // expert MLP (stream 2)
__device__ float g_ue [EL * EI];

// ================= pipelined TF32 tensor-core GEMM =================
// C[M,N] = (ACCUM? C : 0) + A[M,K] @ B[K,N].  fp32 in/out, tf32 mma.
// 256 threads = 8 warps, block tile 64x64, BK=32, cp.async double buffer.
// Warp tile 16x32 (wm=warp>>1 in 0..3, wn=warp&1).
// As[m][k] stride 36 (frag bank = lane), Bs[k][n] stride 72 (bank = 8*tig+gid).
// Requires M%64==0 (512,128 ok), K%16==0, N%16==0 (guards handle 720).

#define GBM 64
#define GBN 64
#define GBK 32
#define ASTRIDE 36
#define BSTRIDE 72

__device__ __forceinline__ uint32_t f2tf32(float x) {
    uint32_t r;
    asm("cvt.rna.tf32.f32 %0, %1;" : "=r"(r) : "f"(x));
    return r;
}

__device__ __forceinline__ void cp_async16(uint32_t dst, const float* src, bool valid) {
    int sz = valid ? 16 : 0;
    asm volatile("cp.async.cg.shared.global [%0], [%1], 16, %2;\n"
                 :: "r"(dst), "l"(src), "r"(sz));
}

template <int ACCUM>
__global__ __launch_bounds__(256)
void tf32_gemm(const float* __restrict__ A, const float* __restrict__ B,
               float* __restrict__ C, int M, int N, int K) {
    __shared__ float As[2][GBM * ASTRIDE];
    __shared__ float Bs[2][GBK * BSTRIDE];

    const int tid  = threadIdx.x;
    const int lane = tid & 31;
    const int warp = tid >> 5;
    const int wm   = warp >> 1;        // 0..3
    const int wn   = warp & 1;         // 0..1
    const int gid  = lane >> 2;        // 0..7
    const int tig  = lane & 3;         // 0..3
    const int m0   = blockIdx.y * GBM;
    const int n0   = blockIdx.x * GBN;

    // loader mapping
    const int am = tid >> 2;           // 0..63
    const int ak = (tid & 3) * 8;      // 0,8,16,24
    const int bk = tid >> 3;           // 0..31
    const int bn = (tid & 7) * 8;      // 0..56

    const float* aSrc = A + (size_t)(m0 + am) * K + ak;
    const float* bSrc = B + (size_t)bk * N + n0 + bn;

    const uint32_t aBase = (uint32_t)__cvta_generic_to_shared(&As[0][0]);
    const uint32_t bBase = (uint32_t)__cvta_generic_to_shared(&Bs[0][0]);
    const uint32_t aDst  = aBase + (uint32_t)(am * ASTRIDE + ak) * 4u;
    const uint32_t bDst  = bBase + (uint32_t)(bk * BSTRIDE + bn) * 4u;
    const uint32_t aBuf  = GBM * ASTRIDE * 4u;
    const uint32_t bBuf  = GBK * BSTRIDE * 4u;

    const int nk = (K + GBK - 1) / GBK;
    const bool nv0 = (n0 + bn) < N;          // N%4==0 -> whole chunk valid or not
    const bool nv1 = (n0 + bn + 4) < N;

    auto issue = [&](int kt) {
        const int buf = kt & 1;
        const int k0  = kt * GBK;
        bool v0 = (k0 + ak) < K;             // K%4==0
        bool v1 = (k0 + ak + 4) < K;
        cp_async16(aDst + buf * aBuf,      v0 ? (aSrc + k0)     : A, v0);
        cp_async16(aDst + buf * aBuf + 16, v1 ? (aSrc + k0 + 4) : A, v1);
        bool kv = (k0 + bk) < K;
        const float* bs = bSrc + (size_t)k0 * N;
        cp_async16(bDst + buf * bBuf,      (kv && nv0) ? bs       : B, kv && nv0);
        cp_async16(bDst + buf * bBuf + 16, (kv && nv1) ? (bs + 4) : B, kv && nv1);
        asm volatile("cp.async.commit_group;\n" ::: "memory");
    };

    float c[4][4] = {};                      // [n8 tile][4 accum regs]

    issue(0);
    if (nk > 1) issue(1);

    for (int kt = 0; kt < nk; kt++) {
        if (kt + 1 < nk)
            asm volatile("cp.async.wait_group 1;\n" ::: "memory");
        else
            asm volatile("cp.async.wait_group 0;\n" ::: "memory");
        __syncthreads();

        const float* as = As[kt & 1];
        const float* bs = Bs[kt & 1];
#pragma unroll
        for (int kk = 0; kk < GBK; kk += 8) {
            uint32_t a[4];
            a[0] = f2tf32(as[(wm * 16 + gid    ) * ASTRIDE + kk + tig    ]);
            a[1] = f2tf32(as[(wm * 16 + gid + 8) * ASTRIDE + kk + tig    ]);
            a[2] = f2tf32(as[(wm * 16 + gid    ) * ASTRIDE + kk + tig + 4]);
            a[3] = f2tf32(as[(wm * 16 + gid + 8) * ASTRIDE + kk + tig + 4]);
            uint32_t b[4][2];
#pragma unroll
            for (int nt = 0; nt < 4; nt++) {
                int nn = wn * 32 + nt * 8 + gid;
                b[nt][0] = f2tf32(bs[(kk + tig    ) * BSTRIDE + nn]);
                b[nt][1] = f2tf32(bs[(kk + tig + 4) * BSTRIDE + nn]);
            }
#pragma unroll
            for (int nt = 0; nt < 4; nt++) {
                asm volatile(
                    "mma.sync.aligned.m16n8k8.row.col.f32.tf32.tf32.f32 "
                    "{%0,%1,%2,%3}, {%4,%5,%6,%7}, {%8,%9}, {%0,%1,%2,%3};"
                    : "+f"(c[nt][0]), "+f"(c[nt][1]),
                      "+f"(c[nt][2]), "+f"(c[nt][3])
                    : "r"(a[0]), "r"(a[1]), "r"(a[2]), "r"(a[3]),
                      "r"(b[nt][0]), "r"(b[nt][1]));
            }
        }
        __syncthreads();
        if (kt + 2 < nk) issue(kt + 2);
    }

    // epilogue
#pragma unroll
    for (int nt = 0; nt < 4; nt++) {
        int gm = m0 + wm * 16 + gid;
        int gn = n0 + wn * 32 + nt * 8 + tig * 2;
        if (gn < N) {
            size_t o0 = (size_t)gm * N + gn;
            size_t o1 = (size_t)(gm + 8) * N + gn;
            if (ACCUM) {
                C[o0]     += c[nt][0];
                C[o0 + 1] += c[nt][1];
                C[o1]     += c[nt][2];
                C[o1 + 1] += c[nt][3];
            } else {
                C[o0]     = c[nt][0];
                C[o0 + 1] = c[nt][1];
                C[o1]     = c[nt][2];
                C[o1 + 1] = c[nt][3];
            }
        }
    }
}

static inline void gemm(const float* A, const float* B, float* C,
                        int M, int N, int K, bool accum, cudaStream_t st) {
    dim3 grid((N + GBN - 1) / GBN, (M + GBM - 1) / GBM);
    if (accum) tf32_gemm<1><<<grid, 256, 0, st>>>(A, B, C, M, N, K);
    else       tf32_gemm<0><<<grid, 256, 0, st>>>(A, B, C, M, N, K);
}

// ---------------- RMSNorm ----------------
__global__ void rmsnorm_kernel(const float* __restrict__ x,
                               const float* __restrict__ w,
                               float* __restrict__ y, int D) {
    const int row = blockIdx.x;
    const float* xr = x + (size_t)row * D;
    float ss = 0.f;
    for (int i = threadIdx.x; i < D; i += 256) { float v = xr[i]; ss += v * v; }
    __shared__ float red[256];
    red[threadIdx.x] = ss;
    __syncthreads();
    for (int s = 128; s > 0; s >>= 1) {
        if (threadIdx.x < s) red[threadIdx.x] += red[threadIdx.x + s];
        __syncthreads();
    }
    float r = rsqrtf(red[0] / (float)D + 1e-5f);
    float* yr = y + (size_t)row * D;
    for (int i = threadIdx.x; i < D; i += 256) yr[i] = w[i] * xr[i] * r;
}

// ---------------- RoPE (in place, pos = pos_base + row) ----------------
__global__ void rope_kernel(float* __restrict__ x, int nrows, int nheads,
                            int pos_base) {
    int idx = blockIdx.x * blockDim.x + threadIdx.x;
    int total = nrows * nheads * 32;
    if (idx >= total) return;
    int d = idx & 31;
    int h = (idx >> 5) % nheads;
    int r = idx / (32 * nheads);
    float pos = (float)(pos_base + r);
    float ts = powf(10000.f, (float)d * (1.f / 32.f));
    float rad = pos / ts;
    float s, c;
    sincosf(rad, &s, &c);
    float* p = x + ((size_t)r * nheads + h) * HD;
    float x1 = p[d], x2 = p[d + 32];
    p[d]      = x1 * c - x2 * s;
    p[d + 32] = x2 * c + x1 * s;
}

// ---------------- Attention (SIMT fp32) ----------------
__global__ __launch_bounds__(128)
void attn_kernel(const float* __restrict__ q, const float* __restrict__ k,
                 const float* __restrict__ v, float* __restrict__ out,
                 int nk, int prefix) {
    const int qi  = blockIdx.x;
    const int h   = blockIdx.y;
    const int kvh = h / 3;
    const int tid = threadIdx.x;

    __shared__ float qs[HD];
    __shared__ float sc[SS];
    __shared__ float red[128];

    const float* qr = q + ((size_t)qi * NH + h) * HD;
    if (tid < HD) qs[tid] = qr[tid];
    __syncthreads();

    int kmax = nk;
    if (prefix) kmax = (qi + 1 > prefix) ? (qi + 1) : prefix;

    float mx = -1e30f;
    for (int j = tid; j < kmax; j += 128) {
        const float* kr = k + ((size_t)j * NKV + kvh) * HD;
        float dot = 0.f;
#pragma unroll
        for (int d = 0; d < HD; d++) dot += qs[d] * kr[d];
        dot *= 0.125f;
        sc[j] = dot;
        mx = fmaxf(mx, dot);
    }
    red[tid] = mx;
    __syncthreads();
    for (int s = 64; s > 0; s >>= 1) {
        if (tid < s) red[tid] = fmaxf(red[tid], red[tid + s]);
        __syncthreads();
    }
    mx = red[0];
    __syncthreads();

    float sum = 0.f;
    for (int j = tid; j < kmax; j += 128) {
        float e = expf(sc[j] - mx);
        sc[j] = e;
        sum += e;
    }
    red[tid] = sum;
    __syncthreads();
    for (int s = 64; s > 0; s >>= 1) {
        if (tid < s) red[tid] += red[tid + s];
        __syncthreads();
    }
    float inv = 1.f / red[0];
    __syncthreads();

    const int d = tid & 63;
    const int half = tid >> 6;
    float acc = 0.f;
    for (int j = half; j < kmax; j += 2)
        acc += sc[j] * v[((size_t)j * NKV + kvh) * HD + d];
    red[tid] = acc;
    __syncthreads();
    if (tid < HD)
        out[((size_t)qi * NH + h) * HD + d] = (red[tid] + red[tid + 64]) * inv;
}

// ---------------- silu(g) * u ----------------
__global__ void silu_mul_kernel(const float* __restrict__ g,
                                const float* __restrict__ u,
                                float* __restrict__ m, int n) {
    int i = blockIdx.x * blockDim.x + threadIdx.x;
    if (i < n) {
        float x = g[i];
        float s = x / (1.f + expf(-x));
        m[i] = s * u[i];
    }
}

// ---------------- launch ----------------
static float* sym(const void* s) {
    void* p = nullptr;
    cudaGetSymbolAddress(&p, s);
    return (float*)p;
}

static cudaStream_t s2;
static cudaEvent_t ev0, evA[LAYERS], evB[LAYERS], evK[LAYERS], evE[LAYERS];
static bool g_inited = false;

static void init_once() {
    if (g_inited) return;
    cudaStreamCreateWithFlags(&s2, cudaStreamNonBlocking);
    cudaEventCreateWithFlags(&ev0, cudaEventDisableTiming);
    for (int i = 0; i < LAYERS; i++) {
        cudaEventCreateWithFlags(&evA[i], cudaEventDisableTiming);
        cudaEventCreateWithFlags(&evB[i], cudaEventDisableTiming);
        cudaEventCreateWithFlags(&evK[i], cudaEventDisableTiming);
        cudaEventCreateWithFlags(&evE[i], cudaEventDisableTiming);
    }
    g_inited = true;
}

extern "C" void kernel_launch(void* const* d_in, const int* in_sizes, int n_in,
                              void* d_out, int out_size) {
    init_once();
    cudaStream_t s0 = 0;

    const float* vlm_embeds    = (const float*)d_in[0];
    const float* expert_embeds = (const float*)d_in[1];
    const float* w_vlm_q       = (const float*)d_in[2];
    const float* w_vlm_k       = (const float*)d_in[3];
    const float* w_vlm_v       = (const float*)d_in[4];
    const float* w_vlm_o       = (const float*)d_in[5];
    const float* w_vlm_ln1     = (const float*)d_in[6];
    const float* w_vlm_ln2     = (const float*)d_in[7];
    const float* w_vlm_gate    = (const float*)d_in[8];
    const float* w_vlm_up      = (const float*)d_in[9];
    const float* w_vlm_down    = (const float*)d_in[10];
    const float* w_vlm_fnorm   = (const float*)d_in[11];
    const float* w_exp_q       = (const float*)d_in[12];
    const float* w_exp_k_self  = (const float*)d_in[13];
    const float* w_exp_v_self  = (const float*)d_in[14];
    const float* w_exp_k_cross = (const float*)d_in[15];
    const float* w_exp_v_cross = (const float*)d_in[16];
    const float* w_exp_o       = (const float*)d_in[17];
    const float* w_exp_ln1     = (const float*)d_in[18];
    const float* w_exp_ln2     = (const float*)d_in[19];
    const float* w_exp_gate    = (const float*)d_in[20];
    const float* w_exp_up      = (const float*)d_in[21];
    const float* w_exp_down    = (const float*)d_in[22];
    const float* w_exp_fnorm   = (const float*)d_in[23];

    float* vlm = sym(g_vlm);
    float* exq = sym(g_exp);
    float* hv  = sym(g_hv);
    float* he  = sym(g_he);
    float* q   = sym(g_q);
    float* k   = sym(g_k);
    float* v   = sym(g_v);
    float* ke  = sym(g_ke);
    float* ve  = sym(g_ve);
    float* att = sym(g_att);
    float* gg  = sym(g_g);
    float* gu  = sym(g_u);
    float* gge = sym(g_ge);
    float* gue = sym(g_ue);

    cudaMemcpyAsync(vlm, vlm_embeds,    (size_t)PL * TH * sizeof(float),
                    cudaMemcpyDeviceToDevice, s0);
    cudaMemcpyAsync(exq, expert_embeds, (size_t)EL * EH * sizeof(float),
                    cudaMemcpyDeviceToDevice, s0);
    cudaEventRecord(ev0, s0);
    cudaStreamWaitEvent(s2, ev0, 0);

    for (int li = 0; li < LAYERS; li++) {
        if ((li & 1) == 0) {
            // ======== EVEN LAYER: joint attention over S=640 ========
            // s2: expert QKV
            rmsnorm_kernel<<<EL, 256, 0, s2>>>(exq, w_exp_ln1 + (size_t)li * EH, he, EH);
            gemm(he, w_exp_q + (size_t)li * EH * (NH * HD),  q + PL * NH * HD,  EL, NH * HD,  EH, false, s2);
            gemm(he, w_exp_k_self + (size_t)(li / 2) * EH * (NKV * HD),
                 k + PL * NKV * HD, EL, NKV * HD, EH, false, s2);
            gemm(he, w_exp_v_self + (size_t)(li / 2) * EH * (NKV * HD),
                 v + PL * NKV * HD, EL, NKV * HD, EH, false, s2);
            cudaEventRecord(evA[li], s2);

            // s0: vlm QKV (must not start before prev-layer s2 readers of v/att done)
            if (li > 0) cudaStreamWaitEvent(s0, evE[li - 1], 0);
            rmsnorm_kernel<<<PL, 256, 0, s0>>>(vlm, w_vlm_ln1 + (size_t)li * TH, hv, TH);
            gemm(hv, w_vlm_q + (size_t)li * TH * (NH * HD),  q, PL, NH * HD,  TH, false, s0);
            gemm(hv, w_vlm_k + (size_t)li * TH * (NKV * HD), k, PL, NKV * HD, TH, false, s0);
            gemm(hv, w_vlm_v + (size_t)li * TH * (NKV * HD), v, PL, NKV * HD, TH, false, s0);

            cudaStreamWaitEvent(s0, evA[li], 0);
            { int t = SS * NH * 32;  rope_kernel<<<(t + 255) / 256, 256, 0, s0>>>(q, SS, NH, 0); }
            { int t = SS * NKV * 32; rope_kernel<<<(t + 255) / 256, 256, 0, s0>>>(k, SS, NKV, 0); }
            attn_kernel<<<dim3(SS, NH), 128, 0, s0>>>(q, k, v, att, SS, PL);
            cudaEventRecord(evB[li], s0);

            // s2: expert block_out (needs att[PL:])
            cudaStreamWaitEvent(s2, evB[li], 0);
            gemm(att + PL * NH * HD, w_exp_o + (size_t)li * (NH * HD) * EH,
                 exq, EL, EH, NH * HD, true, s2);
            rmsnorm_kernel<<<EL, 256, 0, s2>>>(exq, w_exp_ln2 + (size_t)li * EH, he, EH);
            gemm(he, w_exp_gate + (size_t)li * EH * EI, gge, EL, EI, EH, false, s2);
            gemm(he, w_exp_up   + (size_t)li * EH * EI, gue, EL, EI, EH, false, s2);
            silu_mul_kernel<<<(EL * EI + 255) / 256, 256, 0, s2>>>(gge, gue, gge, EL * EI);
            gemm(gge, w_exp_down + (size_t)li * EI * EH, exq, EL, EH, EI, true, s2);
            cudaEventRecord(evE[li], s2);

            // s0: vlm block_out
            gemm(att, w_vlm_o + (size_t)li * (NH * HD) * TH, vlm, PL, TH, NH * HD, true, s0);
            rmsnorm_kernel<<<PL, 256, 0, s0>>>(vlm, w_vlm_ln2 + (size_t)li * TH, hv, TH);
            gemm(hv, w_vlm_gate + (size_t)li * TH * TI, gg, PL, TI, TH, false, s0);
            gemm(hv, w_vlm_up   + (size_t)li * TH * TI, gu, PL, TI, TH, false, s0);
            silu_mul_kernel<<<(PL * TI + 255) / 256, 256, 0, s0>>>(gg, gu, gg, PL * TI);
            gemm(gg, w_vlm_down + (size_t)li * TI * TH, vlm, PL, TH, TI, true, s0);
        } else {
            // ======== ODD LAYER: vlm self-attn + expert cross-attn ========
            // s0: vlm QKV + rope (rows [0,PL) only)
            rmsnorm_kernel<<<PL, 256, 0, s0>>>(vlm, w_vlm_ln1 + (size_t)li * TH, hv, TH);
            gemm(hv, w_vlm_q + (size_t)li * TH * (NH * HD),  q, PL, NH * HD,  TH, false, s0);
            gemm(hv, w_vlm_k + (size_t)li * TH * (NKV * HD), k, PL, NKV * HD, TH, false, s0);
            gemm(hv, w_vlm_v + (size_t)li * TH * (NKV * HD), v, PL, NKV * HD, TH, false, s0);
            { int t = PL * NH * 32;  rope_kernel<<<(t + 255) / 256, 256, 0, s0>>>(q, PL, NH, 0); }
            { int t = PL * NKV * 32; rope_kernel<<<(t + 255) / 256, 256, 0, s0>>>(k, PL, NKV, 0); }
            cudaEventRecord(evK[li], s0);

            // s2: expert q + rope rows [PL,SS), then cross K/V + attn + block_out
            rmsnorm_kernel<<<EL, 256, 0, s2>>>(exq, w_exp_ln1 + (size_t)li * EH, he, EH);
            gemm(he, w_exp_q + (size_t)li * EH * (NH * HD), q + PL * NH * HD, EL, NH * HD, EH, false, s2);
            { int t = EL * NH * 32; rope_kernel<<<(t + 255) / 256, 256, 0, s2>>>(q + PL * NH * HD, EL, NH, PL); }
            cudaStreamWaitEvent(s2, evK[li], 0);
            gemm(k, w_exp_k_cross + (size_t)(li / 2) * (NKV * HD) * (NKV * HD),
                 ke, PL, NKV * HD, NKV * HD, false, s2);
            gemm(v, w_exp_v_cross + (size_t)(li / 2) * (NKV * HD) * (NKV * HD),
                 ve, PL, NKV * HD, NKV * HD, false, s2);
            attn_kernel<<<dim3(EL, NH), 128, 0, s2>>>(q + PL * NH * HD, ke, ve,
                                                      att + PL * NH * HD, PL, 0);
            gemm(att + PL * NH * HD, w_exp_o + (size_t)li * (NH * HD) * EH,
                 exq, EL, EH, NH * HD, true, s2);
            rmsnorm_kernel<<<EL, 256, 0, s2>>>(exq, w_exp_ln2 + (size_t)li * EH, he, EH);
            gemm(he, w_exp_gate + (size_t)li * EH * EI, gge, EL, EI, EH, false, s2);
            gemm(he, w_exp_up   + (size_t)li * EH * EI, gue, EL, EI, EH, false, s2);
            silu_mul_kernel<<<(EL * EI + 255) / 256, 256, 0, s2>>>(gge, gue, gge, EL * EI);
            gemm(gge, w_exp_down + (size_t)li * EI * EH, exq, EL, EH, EI, true, s2);
            cudaEventRecord(evE[li], s2);

            // s0: vlm attention + block_out
            attn_kernel<<<dim3(PL, NH), 128, 0, s0>>>(q, k, v, att, PL, 0);
            gemm(att, w_vlm_o + (size_t)li * (NH * HD) * TH, vlm, PL, TH, NH * HD, true, s0);
            rmsnorm_kernel<<<PL, 256, 0, s0>>>(vlm, w_vlm_ln2 + (size_t)li * TH, hv, TH);
            gemm(hv, w_vlm_gate + (size_t)li * TH * TI, gg, PL, TI, TH, false, s0);
            gemm(hv, w_vlm_up   + (size_t)li * TH * TI, gu, PL, TI, TH, false, s0);
            silu_mul_kernel<<<(PL * TI + 255) / 256, 256, 0, s0>>>(gg, gu, gg, PL * TI);
            gemm(gg, w_vlm_down + (size_t)li * TI * TH, vlm, PL, TH, TI, true, s0);
        }
    }

    // join expert stream, final norms
    cudaStreamWaitEvent(s0, evE[LAYERS - 1], 0);
    float* out = (float*)d_out;
    rmsnorm_kernel<<<PL, 256, 0, s0>>>(vlm, w_vlm_fnorm, out, TH);
    rmsnorm_kernel<<<EL, 256, 0, s0>>>(exq, w_exp_fnorm, out + (size_t)PL * TH, EH);
}

// round 4
// speedup vs baseline: 4.6844x; 2.2854x over previous
#include <cuda_runtime.h>
#include <math.h>
#include <stdint.h>

#define PL 512
#define EL 128
#define SS 640
#define TH 960
#define EH 720
#define TI 2560
#define EI 2048
#define NH 15
#define NKV 5
#define HD 64
#define LAYERS 16

// ---------------- scratch (device globals) ----------------
__device__ float g_vlm[PL * TH];
__device__ float g_exp[EL * EH];
__device__ float g_hv [PL * TH];
__device__ float g_he [EL * EH];
__device__ float g_q  [SS * NH * HD];
__device__ float g_k  [SS * NKV * HD];
__device__ float g_v  [SS * NKV * HD];
__device__ float g_ke [PL * NKV * HD];
__device__ float g_ve [PL * NKV * HD];
__device__ float g_att[SS * NH * HD];
__device__ float g_g  [PL * TI];
__device__ float g_u  [PL * TI];
__device__ float g_ge [EL * EI];
__device__ float g_ue [EL * EI];

// ================= pipelined TF32 tensor-core GEMM =================
// Block tile 128x64, BK=32, 256 threads = 8 warps (warp tile 32x32),
// 3-stage cp.async pipeline, multi-segment launches (up to 3 GEMMs that
// share M and K; each segment has its own A, B, C, N).
// Requires M % 128 == 0 (512, 128), K % 4 == 0, N % 4 == 0.

#define GBK 32
#define ASTRIDE 36
#define BSTRIDE 72
#define AFLOATS (128 * ASTRIDE)      // 4608 floats per stage
#define BFLOATS (GBK * BSTRIDE)      // 2304 floats per stage
#define STAGES 3
#define GEMM_SMEM_BYTES (STAGES * (AFLOATS + BFLOATS) * 4)   // 82944

struct GemmSeg { const float* A; const float* B; float* C; int N; int tiles; };
struct GemmSegs { GemmSeg s[3]; };

__device__ __forceinline__ uint32_t f2tf32(float x) {
    uint32_t r;
    asm("cvt.rna.tf32.f32 %0, %1;" : "=r"(r) : "f"(x));
    return r;
}

__device__ __forceinline__ void cp_async16(uint32_t dst, const float* src, bool valid) {
    int sz = valid ? 16 : 0;
    asm volatile("cp.async.cg.shared.global [%0], [%1], 16, %2;\n"
                 :: "r"(dst), "l"(src), "r"(sz));
}

template <int ACCUM>
__global__ __launch_bounds__(256)
void tf32_gemm(GemmSegs segs, int nseg, int M, int K) {
    extern __shared__ float smem_dyn[];

    // segment select
    int bx = blockIdx.x, si = 0;
    while (si + 1 < nseg && bx >= segs.s[si].tiles) { bx -= segs.s[si].tiles; si++; }
    const float* __restrict__ A = segs.s[si].A;
    const float* __restrict__ B = segs.s[si].B;
    float* __restrict__ C = segs.s[si].C;
    const int N  = segs.s[si].N;
    const int n0 = bx * 64;
    const int m0 = blockIdx.y * 128;

    const int tid  = threadIdx.x;
    const int lane = tid & 31;
    const int warp = tid >> 5;
    const int wm   = warp >> 1;        // 0..3 (32 rows each)
    const int wn   = warp & 1;         // 0..1 (32 cols each)
    const int gid  = lane >> 2;        // 0..7
    const int tig  = lane & 3;         // 0..3

    // loader mapping
    const int am = tid >> 2;           // 0..63 (also row am+64)
    const int ak = (tid & 3) * 8;      // 0,8,16,24
    const int bk = tid >> 3;           // 0..31
    const int bn = (tid & 7) * 8;      // 0..56

    const float* aSrc0 = A + (size_t)(m0 + am) * K + ak;
    const float* aSrc1 = A + (size_t)(m0 + am + 64) * K + ak;
    const float* bSrc  = B + (size_t)bk * N + n0 + bn;

    const uint32_t base = (uint32_t)__cvta_generic_to_shared(smem_dyn);
    const uint32_t aD0 = base + (uint32_t)(am * ASTRIDE + ak) * 4u;
    const uint32_t aD1 = base + (uint32_t)((am + 64) * ASTRIDE + ak) * 4u;
    const uint32_t bD  = base + (uint32_t)(STAGES * AFLOATS + bk * BSTRIDE + bn) * 4u;

    const int nk = (K + GBK - 1) / GBK;
    const bool nv0 = (n0 + bn) < N;
    const bool nv1 = (n0 + bn + 4) < N;

    auto issue = [&](int kt) {
        const int st  = kt % STAGES;
        const uint32_t aOff = (uint32_t)(st * AFLOATS) * 4u;
        const uint32_t bOff = (uint32_t)(st * BFLOATS) * 4u;
        const int k0 = kt * GBK;
        bool v0 = (k0 + ak) < K;
        bool v1 = (k0 + ak + 4) < K;
        cp_async16(aD0 + aOff,      v0 ? (aSrc0 + k0)     : A, v0);
        cp_async16(aD0 + aOff + 16, v1 ? (aSrc0 + k0 + 4) : A, v1);
        cp_async16(aD1 + aOff,      v0 ? (aSrc1 + k0)     : A, v0);
        cp_async16(aD1 + aOff + 16, v1 ? (aSrc1 + k0 + 4) : A, v1);
        bool kv = (k0 + bk) < K;
        const float* bs = bSrc + (size_t)k0 * N;
        cp_async16(bD + bOff,      (kv && nv0) ? bs       : B, kv && nv0);
        cp_async16(bD + bOff + 16, (kv && nv1) ? (bs + 4) : B, kv && nv1);
        asm volatile("cp.async.commit_group;\n" ::: "memory");
    };

    float c[2][4][4] = {};

    issue(0);
    if (nk > 1) issue(1);
    if (nk > 2) issue(2);

    for (int kt = 0; kt < nk; kt++) {
        int rem = nk - kt - 1;
        if (rem >= 2)      asm volatile("cp.async.wait_group 2;\n" ::: "memory");
        else if (rem == 1) asm volatile("cp.async.wait_group 1;\n" ::: "memory");
        else               asm volatile("cp.async.wait_group 0;\n" ::: "memory");
        __syncthreads();

        const float* as = smem_dyn + (kt % STAGES) * AFLOATS;
        const float* bs = smem_dyn + STAGES * AFLOATS + (kt % STAGES) * BFLOATS;

#pragma unroll
        for (int kk = 0; kk < GBK; kk += 8) {
            uint32_t a[2][4];
#pragma unroll
            for (int mt = 0; mt < 2; mt++) {
                int mb = wm * 32 + mt * 16;
                a[mt][0] = f2tf32(as[(mb + gid    ) * ASTRIDE + kk + tig    ]);
                a[mt][1] = f2tf32(as[(mb + gid + 8) * ASTRIDE + kk + tig    ]);
                a[mt][2] = f2tf32(as[(mb + gid    ) * ASTRIDE + kk + tig + 4]);
                a[mt][3] = f2tf32(as[(mb + gid + 8) * ASTRIDE + kk + tig + 4]);
            }
            uint32_t b[4][2];
#pragma unroll
            for (int nt = 0; nt < 4; nt++) {
                int nn = wn * 32 + nt * 8 + gid;
                b[nt][0] = f2tf32(bs[(kk + tig    ) * BSTRIDE + nn]);
                b[nt][1] = f2tf32(bs[(kk + tig + 4) * BSTRIDE + nn]);
            }
#pragma unroll
            for (int mt = 0; mt < 2; mt++)
#pragma unroll
                for (int nt = 0; nt < 4; nt++) {
                    asm volatile(
                        "mma.sync.aligned.m16n8k8.row.col.f32.tf32.tf32.f32 "
                        "{%0,%1,%2,%3}, {%4,%5,%6,%7}, {%8,%9}, {%0,%1,%2,%3};"
                        : "+f"(c[mt][nt][0]), "+f"(c[mt][nt][1]),
                          "+f"(c[mt][nt][2]), "+f"(c[mt][nt][3])
                        : "r"(a[mt][0]), "r"(a[mt][1]),
                          "r"(a[mt][2]), "r"(a[mt][3]),
                          "r"(b[nt][0]), "r"(b[nt][1]));
                }
        }
        __syncthreads();
        if (kt + STAGES < nk) issue(kt + STAGES);
    }

    // epilogue
#pragma unroll
    for (int mt = 0; mt < 2; mt++) {
#pragma unroll
        for (int nt = 0; nt < 4; nt++) {
            int gm = m0 + wm * 32 + mt * 16 + gid;
            int gn = n0 + wn * 32 + nt * 8 + tig * 2;
            if (gn < N) {
                size_t o0 = (size_t)gm * N + gn;
                size_t o1 = (size_t)(gm + 8) * N + gn;
                if (ACCUM) {
                    C[o0]     += c[mt][nt][0];
                    C[o0 + 1] += c[mt][nt][1];
                    C[o1]     += c[mt][nt][2];
                    C[o1 + 1] += c[mt][nt][3];
                } else {
                    C[o0]     = c[mt][nt][0];
                    C[o0 + 1] = c[mt][nt][1];
                    C[o1]     = c[mt][nt][2];
                    C[o1 + 1] = c[mt][nt][3];
                }
            }
        }
    }
}

static inline GemmSeg mkseg(const float* A, const float* B, float* C, int N) {
    GemmSeg s; s.A = A; s.B = B; s.C = C; s.N = N; s.tiles = (N + 63) / 64;
    return s;
}

static void gemmN(const GemmSegs& gs, int nseg, int M, int K, bool accum,
                  cudaStream_t st) {
    int tiles = 0;
    for (int i = 0; i < nseg; i++) tiles += gs.s[i].tiles;
    dim3 grid(tiles, M / 128);
    if (accum) tf32_gemm<1><<<grid, 256, GEMM_SMEM_BYTES, st>>>(gs, nseg, M, K);
    else       tf32_gemm<0><<<grid, 256, GEMM_SMEM_BYTES, st>>>(gs, nseg, M, K);
}

static void gemm1(const float* A, const float* B, float* C, int M, int N, int K,
                  bool accum, cudaStream_t st) {
    GemmSegs gs = {};
    gs.s[0] = mkseg(A, B, C, N);
    gemmN(gs, 1, M, K, accum, st);
}

// ---------------- RMSNorm ----------------
__global__ void rmsnorm_kernel(const float* __restrict__ x,
                               const float* __restrict__ w,
                               float* __restrict__ y, int D) {
    const int row = blockIdx.x;
    const float* xr = x + (size_t)row * D;
    float ss = 0.f;
    for (int i = threadIdx.x; i < D; i += 256) { float v = xr[i]; ss += v * v; }
    __shared__ float red[256];
    red[threadIdx.x] = ss;
    __syncthreads();
    for (int s = 128; s > 0; s >>= 1) {
        if (threadIdx.x < s) red[threadIdx.x] += red[threadIdx.x + s];
        __syncthreads();
    }
    float r = rsqrtf(red[0] / (float)D + 1e-5f);
    float* yr = y + (size_t)row * D;
    for (int i = threadIdx.x; i < D; i += 256) yr[i] = w[i] * xr[i] * r;
}

// ---------------- RoPE (in place, pos = pos_base + row) ----------------
__global__ void rope_kernel(float* __restrict__ x, int nrows, int nheads,
                            int pos_base) {
    int idx = blockIdx.x * blockDim.x + threadIdx.x;
    int total = nrows * nheads * 32;
    if (idx >= total) return;
    int d = idx & 31;
    int h = (idx >> 5) % nheads;
    int r = idx / (32 * nheads);
    float pos = (float)(pos_base + r);
    float ts = powf(10000.f, (float)d * (1.f / 32.f));
    float rad = pos / ts;
    float s, c;
    sincosf(rad, &s, &c);
    float* p = x + ((size_t)r * nheads + h) * HD;
    float x1 = p[d], x2 = p[d + 32];
    p[d]      = x1 * c - x2 * s;
    p[d + 32] = x2 * c + x1 * s;
}

// ---------------- Attention (SIMT fp32) ----------------
__global__ __launch_bounds__(128)
void attn_kernel(const float* __restrict__ q, const float* __restrict__ k,
                 const float* __restrict__ v, float* __restrict__ out,
                 int nk, int prefix) {
    const int qi  = blockIdx.x;
    const int h   = blockIdx.y;
    const int kvh = h / 3;
    const int tid = threadIdx.x;

    __shared__ float qs[HD];
    __shared__ float sc[SS];
    __shared__ float red[128];

    const float* qr = q + ((size_t)qi * NH + h) * HD;
    if (tid < HD) qs[tid] = qr[tid];
    __syncthreads();

    int kmax = nk;
    if (prefix) kmax = (qi + 1 > prefix) ? (qi + 1) : prefix;

    const float4* q4 = (const float4*)qs;
    float mx = -1e30f;
    for (int j = tid; j < kmax; j += 128) {
        const float4* k4 = (const float4*)(k + ((size_t)j * NKV + kvh) * HD);
        float dot = 0.f;
#pragma unroll
        for (int d = 0; d < 16; d++) {
            float4 kk = k4[d], qq = q4[d];
            dot += qq.x * kk.x + qq.y * kk.y + qq.z * kk.z + qq.w * kk.w;
        }
        dot *= 0.125f;
        sc[j] = dot;
        mx = fmaxf(mx, dot);
    }
    red[tid] = mx;
    __syncthreads();
    for (int s = 64; s > 0; s >>= 1) {
        if (tid < s) red[tid] = fmaxf(red[tid], red[tid + s]);
        __syncthreads();
    }
    mx = red[0];
    __syncthreads();

    float sum = 0.f;
    for (int j = tid; j < kmax; j += 128) {
        float e = expf(sc[j] - mx);
        sc[j] = e;
        sum += e;
    }
    red[tid] = sum;
    __syncthreads();
    for (int s = 64; s > 0; s >>= 1) {
        if (tid < s) red[tid] += red[tid + s];
        __syncthreads();
    }
    float inv = 1.f / red[0];
    __syncthreads();

    const int d = tid & 63;
    const int half = tid >> 6;
    float acc = 0.f;
    for (int j = half; j < kmax; j += 2)
        acc += sc[j] * v[((size_t)j * NKV + kvh) * HD + d];
    red[tid] = acc;
    __syncthreads();
    if (tid < HD)
        out[((size_t)qi * NH + h) * HD + d] = (red[tid] + red[tid + 64]) * inv;
}

// ---------------- silu(g) * u ----------------
__global__ void silu_mul_kernel(const float* __restrict__ g,
                                const float* __restrict__ u,
                                float* __restrict__ m, int n) {
    int i = blockIdx.x * blockDim.x + threadIdx.x;
    if (i < n) {
        float x = g[i];
        float s = x / (1.f + expf(-x));
        m[i] = s * u[i];
    }
}

// ---------------- launch ----------------
static float* sym(const void* s) {
    void* p = nullptr;
    cudaGetSymbolAddress(&p, s);
    return (float*)p;
}

static cudaStream_t s2;
static cudaEvent_t ev0, evA[LAYERS], evB[LAYERS], evK[LAYERS], evE[LAYERS];
static bool g_inited = false;

static void init_once() {
    if (g_inited) return;
    cudaStreamCreateWithFlags(&s2, cudaStreamNonBlocking);
    cudaEventCreateWithFlags(&ev0, cudaEventDisableTiming);
    for (int i = 0; i < LAYERS; i++) {
        cudaEventCreateWithFlags(&evA[i], cudaEventDisableTiming);
        cudaEventCreateWithFlags(&evB[i], cudaEventDisableTiming);
        cudaEventCreateWithFlags(&evK[i], cudaEventDisableTiming);
        cudaEventCreateWithFlags(&evE[i], cudaEventDisableTiming);
    }
    cudaFuncSetAttribute(tf32_gemm<0>, cudaFuncAttributeMaxDynamicSharedMemorySize,
                         GEMM_SMEM_BYTES);
    cudaFuncSetAttribute(tf32_gemm<1>, cudaFuncAttributeMaxDynamicSharedMemorySize,
                         GEMM_SMEM_BYTES);
    g_inited = true;
}

extern "C" void kernel_launch(void* const* d_in, const int* in_sizes, int n_in,
                              void* d_out, int out_size) {
    init_once();
    cudaStream_t s0 = 0;

    const float* vlm_embeds    = (const float*)d_in[0];
    const float* expert_embeds = (const float*)d_in[1];
    const float* w_vlm_q       = (const float*)d_in[2];
    const float* w_vlm_k       = (const float*)d_in[3];
    const float* w_vlm_v       = (const float*)d_in[4];
    const float* w_vlm_o       = (const float*)d_in[5];
    const float* w_vlm_ln1     = (const float*)d_in[6];
    const float* w_vlm_ln2     = (const float*)d_in[7];
    const float* w_vlm_gate    = (const float*)d_in[8];
    const float* w_vlm_up      = (const float*)d_in[9];
    const float* w_vlm_down    = (const float*)d_in[10];
    const float* w_vlm_fnorm   = (const float*)d_in[11];
    const float* w_exp_q       = (const float*)d_in[12];
    const float* w_exp_k_self  = (const float*)d_in[13];
    const float* w_exp_v_self  = (const float*)d_in[14];
    const float* w_exp_k_cross = (const float*)d_in[15];
    const float* w_exp_v_cross = (const float*)d_in[16];
    const float* w_exp_o       = (const float*)d_in[17];
    const float* w_exp_ln1     = (const float*)d_in[18];
    const float* w_exp_ln2     = (const float*)d_in[19];
    const float* w_exp_gate    = (const float*)d_in[20];
    const float* w_exp_up      = (const float*)d_in[21];
    const float* w_exp_down    = (const float*)d_in[22];
    const float* w_exp_fnorm   = (const float*)d_in[23];

    float* vlm = sym(g_vlm);
    float* exq = sym(g_exp);
    float* hv  = sym(g_hv);
    float* he  = sym(g_he);
    float* q   = sym(g_q);
    float* k   = sym(g_k);
    float* v   = sym(g_v);
    float* ke  = sym(g_ke);
    float* ve  = sym(g_ve);
    float* att = sym(g_att);
    float* gg  = sym(g_g);
    float* gu  = sym(g_u);
    float* gge = sym(g_ge);
    float* gue = sym(g_ue);

    cudaMemcpyAsync(vlm, vlm_embeds,    (size_t)PL * TH * sizeof(float),
                    cudaMemcpyDeviceToDevice, s0);
    cudaMemcpyAsync(exq, expert_embeds, (size_t)EL * EH * sizeof(float),
                    cudaMemcpyDeviceToDevice, s0);
    cudaEventRecord(ev0, s0);
    cudaStreamWaitEvent(s2, ev0, 0);

    for (int li = 0; li < LAYERS; li++) {
        if ((li & 1) == 0) {
            // ======== EVEN LAYER: joint attention over S=640 ========
            // s2: expert QKV (fused, rows [PL,SS))
            rmsnorm_kernel<<<EL, 256, 0, s2>>>(exq, w_exp_ln1 + (size_t)li * EH, he, EH);
            {
                GemmSegs gs = {};
                gs.s[0] = mkseg(he, w_exp_q + (size_t)li * EH * (NH * HD),
                                q + PL * NH * HD, NH * HD);
                gs.s[1] = mkseg(he, w_exp_k_self + (size_t)(li / 2) * EH * (NKV * HD),
                                k + PL * NKV * HD, NKV * HD);
                gs.s[2] = mkseg(he, w_exp_v_self + (size_t)(li / 2) * EH * (NKV * HD),
                                v + PL * NKV * HD, NKV * HD);
                gemmN(gs, 3, EL, EH, false, s2);
            }
            cudaEventRecord(evA[li], s2);

            // s0: vlm QKV (fused)
            if (li > 0) cudaStreamWaitEvent(s0, evE[li - 1], 0);
            rmsnorm_kernel<<<PL, 256, 0, s0>>>(vlm, w_vlm_ln1 + (size_t)li * TH, hv, TH);
            {
                GemmSegs gs = {};
                gs.s[0] = mkseg(hv, w_vlm_q + (size_t)li * TH * (NH * HD),  q, NH * HD);
                gs.s[1] = mkseg(hv, w_vlm_k + (size_t)li * TH * (NKV * HD), k, NKV * HD);
                gs.s[2] = mkseg(hv, w_vlm_v + (size_t)li * TH * (NKV * HD), v, NKV * HD);
                gemmN(gs, 3, PL, TH, false, s0);
            }

            cudaStreamWaitEvent(s0, evA[li], 0);
            { int t = SS * NH * 32;  rope_kernel<<<(t + 255) / 256, 256, 0, s0>>>(q, SS, NH, 0); }
            { int t = SS * NKV * 32; rope_kernel<<<(t + 255) / 256, 256, 0, s0>>>(k, SS, NKV, 0); }
            attn_kernel<<<dim3(SS, NH), 128, 0, s0>>>(q, k, v, att, SS, PL);
            cudaEventRecord(evB[li], s0);

            // s2: expert block_out
            cudaStreamWaitEvent(s2, evB[li], 0);
            gemm1(att + PL * NH * HD, w_exp_o + (size_t)li * (NH * HD) * EH,
                  exq, EL, EH, NH * HD, true, s2);
            rmsnorm_kernel<<<EL, 256, 0, s2>>>(exq, w_exp_ln2 + (size_t)li * EH, he, EH);
            {
                GemmSegs gs = {};
                gs.s[0] = mkseg(he, w_exp_gate + (size_t)li * EH * EI, gge, EI);
                gs.s[1] = mkseg(he, w_exp_up   + (size_t)li * EH * EI, gue, EI);
                gemmN(gs, 2, EL, EH, false, s2);
            }
            silu_mul_kernel<<<(EL * EI + 255) / 256, 256, 0, s2>>>(gge, gue, gge, EL * EI);
            gemm1(gge, w_exp_down + (size_t)li * EI * EH, exq, EL, EH, EI, true, s2);
            cudaEventRecord(evE[li], s2);

            // s0: vlm block_out
            gemm1(att, w_vlm_o + (size_t)li * (NH * HD) * TH, vlm, PL, TH, NH * HD, true, s0);
            rmsnorm_kernel<<<PL, 256, 0, s0>>>(vlm, w_vlm_ln2 + (size_t)li * TH, hv, TH);
            {
                GemmSegs gs = {};
                gs.s[0] = mkseg(hv, w_vlm_gate + (size_t)li * TH * TI, gg, TI);
                gs.s[1] = mkseg(hv, w_vlm_up   + (size_t)li * TH * TI, gu, TI);
                gemmN(gs, 2, PL, TH, false, s0);
            }
            silu_mul_kernel<<<(PL * TI + 255) / 256, 256, 0, s0>>>(gg, gu, gg, PL * TI);
            gemm1(gg, w_vlm_down + (size_t)li * TI * TH, vlm, PL, TH, TI, true, s0);
        } else {
            // ======== ODD LAYER: vlm self-attn + expert cross-attn ========
            // s0: vlm QKV (fused) + rope rows [0,PL)
            rmsnorm_kernel<<<PL, 256, 0, s0>>>(vlm, w_vlm_ln1 + (size_t)li * TH, hv, TH);
            {
                GemmSegs gs = {};
                gs.s[0] = mkseg(hv, w_vlm_q + (size_t)li * TH * (NH * HD),  q, NH * HD);
                gs.s[1] = mkseg(hv, w_vlm_k + (size_t)li * TH * (NKV * HD), k, NKV * HD);
                gs.s[2] = mkseg(hv, w_vlm_v + (size_t)li * TH * (NKV * HD), v, NKV * HD);
                gemmN(gs, 3, PL, TH, false, s0);
            }
            { int t = PL * NH * 32;  rope_kernel<<<(t + 255) / 256, 256, 0, s0>>>(q, PL, NH, 0); }
            { int t = PL * NKV * 32; rope_kernel<<<(t + 255) / 256, 256, 0, s0>>>(k, PL, NKV, 0); }
            cudaEventRecord(evK[li], s0);

            // s2: expert q + rope, cross K/V (fused, different A per seg), attn, block_out
            rmsnorm_kernel<<<EL, 256, 0, s2>>>(exq, w_exp_ln1 + (size_t)li * EH, he, EH);
            gemm1(he, w_exp_q + (size_t)li * EH * (NH * HD), q + PL * NH * HD,
                  EL, NH * HD, EH, false, s2);
            { int t = EL * NH * 32; rope_kernel<<<(t + 255) / 256, 256, 0, s2>>>(q + PL * NH * HD, EL, NH, PL); }
            cudaStreamWaitEvent(s2, evK[li], 0);
            {
                GemmSegs gs = {};
                gs.s[0] = mkseg(k, w_exp_k_cross + (size_t)(li / 2) * (NKV * HD) * (NKV * HD),
                                ke, NKV * HD);
                gs.s[1] = mkseg(v, w_exp_v_cross + (size_t)(li / 2) * (NKV * HD) * (NKV * HD),
                                ve, NKV * HD);
                gemmN(gs, 2, PL, NKV * HD, false, s2);
            }
            attn_kernel<<<dim3(EL, NH), 128, 0, s2>>>(q + PL * NH * HD, ke, ve,
                                                      att + PL * NH * HD, PL, 0);
            gemm1(att + PL * NH * HD, w_exp_o + (size_t)li * (NH * HD) * EH,
                  exq, EL, EH, NH * HD, true, s2);
            rmsnorm_kernel<<<EL, 256, 0, s2>>>(exq, w_exp_ln2 + (size_t)li * EH, he, EH);
            {
                GemmSegs gs = {};
                gs.s[0] = mkseg(he, w_exp_gate + (size_t)li * EH * EI, gge, EI);
                gs.s[1] = mkseg(he, w_exp_up   + (size_t)li * EH * EI, gue, EI);
                gemmN(gs, 2, EL, EH, false, s2);
            }
            silu_mul_kernel<<<(EL * EI + 255) / 256, 256, 0, s2>>>(gge, gue, gge, EL * EI);
            gemm1(gge, w_exp_down + (size_t)li * EI * EH, exq, EL, EH, EI, true, s2);
            cudaEventRecord(evE[li], s2);

            // s0: vlm attention + block_out
            attn_kernel<<<dim3(PL, NH), 128, 0, s0>>>(q, k, v, att, PL, 0);
            gemm1(att, w_vlm_o + (size_t)li * (NH * HD) * TH, vlm, PL, TH, NH * HD, true, s0);
            rmsnorm_kernel<<<PL, 256, 0, s0>>>(vlm, w_vlm_ln2 + (size_t)li * TH, hv, TH);
            {
                GemmSegs gs = {};
                gs.s[0] = mkseg(hv, w_vlm_gate + (size_t)li * TH * TI, gg, TI);
                gs.s[1] = mkseg(hv, w_vlm_up   + (size_t)li * TH * TI, gu, TI);
                gemmN(gs, 2, PL, TH, false, s0);
            }
            silu_mul_kernel<<<(PL * TI + 255) / 256, 256, 0, s0>>>(gg, gu, gg, PL * TI);
            gemm1(gg, w_vlm_down + (size_t)li * TI * TH, vlm, PL, TH, TI, true, s0);
        }
    }

    // join expert stream, final norms
    cudaStreamWaitEvent(s0, evE[LAYERS - 1], 0);
    float* out = (float*)d_out;
    rmsnorm_kernel<<<PL, 256, 0, s0>>>(vlm, w_vlm_fnorm, out, TH);
    rmsnorm_kernel<<<EL, 256, 0, s0>>>(exq, w_exp_fnorm, out + (size_t)PL * TH, EH);
}